// round 1
// baseline (speedup 1.0000x reference)
#include <cuda_runtime.h>

// SwinMSA fused kernel — fp32 scalar baseline (round 1).
// B=16, WN=4096, S=10, E=96, H=4, dh=24.
// One CTA (288 threads) processes WPB=2 windows end-to-end:
//   phase 1: qkv = X @ W_qkv + b  (q pre-scaled by dh^-0.5)
//   phase 2: windowed attention with relative position bias + shift mask
//   phase 3: out = ctx @ W_o + b_o

#define S_   10
#define E_   96
#define H_   4
#define DH_  24
#define N3_  288
#define WPB  2
#define PAD  25          // row pad for q/k/v smem (conflict-free lane-strided reads)
#define WN_  4096
#define NTHREADS 288

__global__ __launch_bounds__(NTHREADS)
void swin_msa_kernel(const float* __restrict__ X,
                     const float* __restrict__ Wqkv,
                     const float* __restrict__ bqkv,
                     const float* __restrict__ Wo,
                     const float* __restrict__ bo,
                     const float* __restrict__ posb,
                     float* __restrict__ out)
{
    __shared__ __align__(16) float xs[WPB * S_ * E_];      // X tiles, reused as context
    __shared__ float sQ[WPB * H_ * S_ * PAD];
    __shared__ float sK[WPB * H_ * S_ * PAD];
    __shared__ float sV[WPB * H_ * S_ * PAD];
    __shared__ float spb[(2 * S_ - 1) * H_];               // 19 x 4 pos bias

    const int tid = threadIdx.x;
    const long wbase = (long)blockIdx.x * WPB;             // first window id

    // ---- load X tiles + pos bias ----
    {
        const float* gX = X + wbase * (S_ * E_);
        #pragma unroll
        for (int i = tid; i < WPB * S_ * E_; i += NTHREADS)
            xs[i] = gX[i];
        if (tid < (2 * S_ - 1) * H_)
            spb[tid] = posb[tid];
    }
    __syncthreads();

    // ---- phase 1: qkv projection ----
    {
        const int c = tid;               // 0..287 output column of W_qkv
        const int p = c / E_;            // 0=q 1=k 2=v
        const int rem = c - p * E_;
        const int h = rem / DH_;
        const int d = rem - h * DH_;

        float acc[WPB][S_];
        const float b = bqkv[c];
        #pragma unroll
        for (int wi = 0; wi < WPB; wi++)
            #pragma unroll
            for (int r = 0; r < S_; r++)
                acc[wi][r] = b;

        #pragma unroll 4
        for (int k0 = 0; k0 < E_; k0 += 4) {
            const float w0 = Wqkv[(k0 + 0) * N3_ + c];
            const float w1 = Wqkv[(k0 + 1) * N3_ + c];
            const float w2 = Wqkv[(k0 + 2) * N3_ + c];
            const float w3 = Wqkv[(k0 + 3) * N3_ + c];
            #pragma unroll
            for (int wi = 0; wi < WPB; wi++) {
                #pragma unroll
                for (int r = 0; r < S_; r++) {
                    const float4 x4 = *(const float4*)&xs[(wi * S_ + r) * E_ + k0];
                    acc[wi][r] += x4.x * w0 + x4.y * w1 + x4.z * w2 + x4.w * w3;
                }
            }
        }

        const float sc = (p == 0) ? 0.20412414523193154f /* 24^-0.5 */ : 1.0f;
        float* dst = (p == 0) ? sQ : (p == 1) ? sK : sV;
        #pragma unroll
        for (int wi = 0; wi < WPB; wi++)
            #pragma unroll
            for (int r = 0; r < S_; r++)
                dst[((wi * H_ + h) * S_ + r) * PAD + d] = acc[wi][r] * sc;
    }
    __syncthreads();

    // ---- phase 2: attention (warp = (window, head), lane = query row) ----
    {
        const int warp = tid >> 5;
        const int lane = tid & 31;
        if (warp < WPB * H_ && lane < S_) {
            const int wi = warp / H_;
            const int h  = warp % H_;
            const int q  = lane;
            const float* qrow = &sQ[((wi * H_ + h) * S_ + q) * PAD];
            float qv[DH_];
            #pragma unroll
            for (int d = 0; d < DH_; d++) qv[d] = qrow[d];

            const bool masked = (((wbase + wi) & (WN_ - 1)) == (WN_ - 1));

            float row[S_];
            #pragma unroll
            for (int kk = 0; kk < S_; kk++) {
                const float* krow = &sK[((wi * H_ + h) * S_ + kk) * PAD];
                float s = 0.0f;
                #pragma unroll
                for (int d = 0; d < DH_; d++) s += qv[d] * krow[d];
                s += spb[(kk - q + S_ - 1) * H_ + h];
                if (masked && ((q < 5) != (kk < 5))) s -= 100.0f;
                row[kk] = s;
            }

            float m = row[0];
            #pragma unroll
            for (int kk = 1; kk < S_; kk++) m = fmaxf(m, row[kk]);
            float sum = 0.0f;
            #pragma unroll
            for (int kk = 0; kk < S_; kk++) { row[kk] = __expf(row[kk] - m); sum += row[kk]; }
            const float inv = 1.0f / sum;

            // context -> reuse xs as (wi, q, h*DH+d)
            const float* vbase = &sV[(wi * H_ + h) * S_ * PAD];
            #pragma unroll
            for (int d = 0; d < DH_; d++) {
                float o = 0.0f;
                #pragma unroll
                for (int kk = 0; kk < S_; kk++) o += row[kk] * vbase[kk * PAD + d];
                xs[(wi * S_ + q) * E_ + h * DH_ + d] = o * inv;
            }
        }
    }
    __syncthreads();

    // ---- phase 3: output projection ----
    {
        const int c = tid % E_;          // output column
        const int g = tid / E_;          // row group 0..2, rows g, g+3, g+6, ...
        float acc[7];
        const float b = bo[c];
        #pragma unroll
        for (int i = 0; i < 7; i++) acc[i] = b;

        #pragma unroll 4
        for (int k0 = 0; k0 < E_; k0 += 4) {
            const float w0 = Wo[(k0 + 0) * E_ + c];
            const float w1 = Wo[(k0 + 1) * E_ + c];
            const float w2 = Wo[(k0 + 2) * E_ + c];
            const float w3 = Wo[(k0 + 3) * E_ + c];
            int r = g;
            #pragma unroll
            for (int i = 0; i < 7; i++) {
                if (r < WPB * S_) {
                    const float4 x4 = *(const float4*)&xs[r * E_ + k0];
                    acc[i] += x4.x * w0 + x4.y * w1 + x4.z * w2 + x4.w * w3;
                }
                r += 3;
            }
        }

        float* gout = out + wbase * (S_ * E_);
        int r = g;
        #pragma unroll
        for (int i = 0; i < 7; i++) {
            if (r < WPB * S_) gout[r * E_ + c] = acc[i];
            r += 3;
        }
    }
}

extern "C" void kernel_launch(void* const* d_in, const int* in_sizes, int n_in,
                              void* d_out, int out_size)
{
    const float* X    = (const float*)d_in[0];
    const float* Wqkv = (const float*)d_in[1];
    const float* bqkv = (const float*)d_in[2];
    const float* Wo   = (const float*)d_in[3];
    const float* bo   = (const float*)d_in[4];
    const float* posb = (const float*)d_in[5];
    float* out = (float*)d_out;

    const int n_windows = in_sizes[0] / (S_ * E_);   // 65536
    const int grid = n_windows / WPB;                // 32768

    swin_msa_kernel<<<grid, NTHREADS>>>(X, Wqkv, bqkv, Wo, bo, posb, out);
}

// round 4
// speedup vs baseline: 1.3713x; 1.3713x over previous
#include <cuda_runtime.h>

// SwinMSA fused kernel — round 2: register-tiled scalar (2 cols/thread).
// B=16, WN=4096, S=10, E=96, H=4, dh=24.
// One CTA (288 threads) processes WPB=4 windows:
//   phase 1: qkv = X @ W_qkv + b   (thread = 2 cols x 2 windows x 10 rows)
//   phase 2: windowed attention w/ rel-pos bias + shift mask (thread = (wi,h,q))
//   phase 3: out = ctx @ W_o + b_o (thread = 2 cols x 7 row-slots)

#define S_   10
#define E_   96
#define H_   4
#define DH_  24
#define N3_  288
#define WPB  4
#define PAD  25
#define WN_  4096
#define NTHREADS 288

__global__ __launch_bounds__(NTHREADS, 3)
void swin_msa_kernel(const float* __restrict__ X,
                     const float* __restrict__ Wqkv,
                     const float* __restrict__ bqkv,
                     const float* __restrict__ Wo,
                     const float* __restrict__ bo,
                     const float* __restrict__ posb,
                     float* __restrict__ out)
{
    __shared__ __align__(16) float xs[WPB * S_ * E_];      // 3840 f: X tiles, reused as ctx
    __shared__ float sQ[WPB * H_ * S_ * PAD];              // 4000 f
    __shared__ float sK[WPB * H_ * S_ * PAD];
    __shared__ float sV[WPB * H_ * S_ * PAD];
    __shared__ float spb[(2 * S_ - 1) * H_];               // 76 f

    const int tid = threadIdx.x;
    const long wbase = (long)blockIdx.x * WPB;

    // ---- load X tiles (float4) + pos bias ----
    {
        const float4* gX4 = (const float4*)(X + wbase * (S_ * E_));
        #pragma unroll
        for (int i = tid; i < WPB * S_ * E_ / 4; i += NTHREADS)
            ((float4*)xs)[i] = gX4[i];
        if (tid < (2 * S_ - 1) * H_)
            spb[tid] = posb[tid];
    }
    __syncthreads();

    // ---- phase 1: qkv projection, 2 cols x 2 windows x 10 rows per thread ----
    {
        const int half = tid / 144;          // which window pair (0: w0-1, 1: w2-3)
        const int cidx = tid - half * 144;
        const int c0 = cidx;
        const int c1 = cidx + 144;
        const int wib = half * 2;

        float acc0[2][S_], acc1[2][S_];
        {
            const float b0 = bqkv[c0];
            const float b1 = bqkv[c1];
            #pragma unroll
            for (int wl = 0; wl < 2; wl++)
                #pragma unroll
                for (int r = 0; r < S_; r++) { acc0[wl][r] = b0; acc1[wl][r] = b1; }
        }

        #pragma unroll 2
        for (int k0 = 0; k0 < E_; k0 += 4) {
            float wa0 = Wqkv[(k0 + 0) * N3_ + c0];
            float wa1 = Wqkv[(k0 + 1) * N3_ + c0];
            float wa2 = Wqkv[(k0 + 2) * N3_ + c0];
            float wa3 = Wqkv[(k0 + 3) * N3_ + c0];
            float wb0 = Wqkv[(k0 + 0) * N3_ + c1];
            float wb1 = Wqkv[(k0 + 1) * N3_ + c1];
            float wb2 = Wqkv[(k0 + 2) * N3_ + c1];
            float wb3 = Wqkv[(k0 + 3) * N3_ + c1];
            #pragma unroll
            for (int wl = 0; wl < 2; wl++) {
                #pragma unroll
                for (int r = 0; r < S_; r++) {
                    const float4 x4 = *(const float4*)&xs[((wib + wl) * S_ + r) * E_ + k0];
                    acc0[wl][r] += x4.x * wa0 + x4.y * wa1 + x4.z * wa2 + x4.w * wa3;
                    acc1[wl][r] += x4.x * wb0 + x4.y * wb1 + x4.z * wb2 + x4.w * wb3;
                }
            }
        }

        #pragma unroll
        for (int cc = 0; cc < 2; cc++) {
            const int c = cc ? c1 : c0;
            const int p = c / E_;
            const int rem = c - p * E_;
            const int h = rem / DH_;
            const int d = rem - h * DH_;
            const float sc = (p == 0) ? 0.20412414523193154f /* 24^-0.5 */ : 1.0f;
            float* dst = (p == 0) ? sQ : (p == 1) ? sK : sV;
            #pragma unroll
            for (int wl = 0; wl < 2; wl++)
                #pragma unroll
                for (int r = 0; r < S_; r++)
                    dst[(((wib + wl) * H_ + h) * S_ + r) * PAD + d] =
                        (cc ? acc1[wl][r] : acc0[wl][r]) * sc;
        }
    }
    __syncthreads();

    // ---- phase 2: attention, thread = (wi, h, q), 160 active threads ----
    if (tid < WPB * H_ * S_) {
        const int wi = tid / (H_ * S_);
        const int rem = tid - wi * (H_ * S_);
        const int h = rem / S_;
        const int q = rem - h * S_;

        const float* qrow = &sQ[((wi * H_ + h) * S_ + q) * PAD];
        float qv[DH_];
        #pragma unroll
        for (int d = 0; d < DH_; d++) qv[d] = qrow[d];

        const bool masked = (((wbase + wi) & (WN_ - 1)) == (WN_ - 1));

        float row[S_];
        #pragma unroll
        for (int kk = 0; kk < S_; kk++) {
            const float* krow = &sK[((wi * H_ + h) * S_ + kk) * PAD];
            float s = 0.0f;
            #pragma unroll
            for (int d = 0; d < DH_; d++) s += qv[d] * krow[d];
            s += spb[(kk - q + S_ - 1) * H_ + h];
            if (masked && ((q < 5) != (kk < 5))) s -= 100.0f;
            row[kk] = s;
        }

        float m = row[0];
        #pragma unroll
        for (int kk = 1; kk < S_; kk++) m = fmaxf(m, row[kk]);
        float sum = 0.0f;
        #pragma unroll
        for (int kk = 0; kk < S_; kk++) { row[kk] = __expf(row[kk] - m); sum += row[kk]; }
        const float inv = 1.0f / sum;

        const float* vbase = &sV[(wi * H_ + h) * S_ * PAD];
        #pragma unroll
        for (int d = 0; d < DH_; d++) {
            float o = 0.0f;
            #pragma unroll
            for (int kk = 0; kk < S_; kk++) o += row[kk] * vbase[kk * PAD + d];
            xs[(wi * S_ + q) * E_ + h * DH_ + d] = o * inv;
        }
    }
    __syncthreads();

    // ---- phase 3: output projection, 2 cols x 7 row-slots per thread ----
    {
        const int cp = tid % 48;
        const int rg = tid / 48;             // 0..5, rows rg + 6*i
        const int c0 = cp;
        const int c1 = cp + 48;

        float acc0[7], acc1[7];
        {
            const float b0 = bo[c0];
            const float b1 = bo[c1];
            #pragma unroll
            for (int i = 0; i < 7; i++) { acc0[i] = b0; acc1[i] = b1; }
        }

        #pragma unroll 2
        for (int k0 = 0; k0 < E_; k0 += 4) {
            float wa0 = Wo[(k0 + 0) * E_ + c0];
            float wa1 = Wo[(k0 + 1) * E_ + c0];
            float wa2 = Wo[(k0 + 2) * E_ + c0];
            float wa3 = Wo[(k0 + 3) * E_ + c0];
            float wb0 = Wo[(k0 + 0) * E_ + c1];
            float wb1 = Wo[(k0 + 1) * E_ + c1];
            float wb2 = Wo[(k0 + 2) * E_ + c1];
            float wb3 = Wo[(k0 + 3) * E_ + c1];
            int r = rg;
            #pragma unroll
            for (int i = 0; i < 7; i++) {
                if (r < WPB * S_) {
                    const float4 x4 = *(const float4*)&xs[r * E_ + k0];
                    acc0[i] += x4.x * wa0 + x4.y * wa1 + x4.z * wa2 + x4.w * wa3;
                    acc1[i] += x4.x * wb0 + x4.y * wb1 + x4.z * wb2 + x4.w * wb3;
                }
                r += 6;
            }
        }

        float* gout = out + wbase * (S_ * E_);
        int r = rg;
        #pragma unroll
        for (int i = 0; i < 7; i++) {
            if (r < WPB * S_) {
                gout[r * E_ + c0] = acc0[i];
                gout[r * E_ + c1] = acc1[i];
            }
            r += 6;
        }
    }
}

extern "C" void kernel_launch(void* const* d_in, const int* in_sizes, int n_in,
                              void* d_out, int out_size)
{
    const float* X    = (const float*)d_in[0];
    const float* Wqkv = (const float*)d_in[1];
    const float* bqkv = (const float*)d_in[2];
    const float* Wo   = (const float*)d_in[3];
    const float* bo   = (const float*)d_in[4];
    const float* posb = (const float*)d_in[5];
    float* out = (float*)d_out;

    const int n_windows = in_sizes[0] / (S_ * E_);   // 65536
    const int grid = n_windows / WPB;                // 16384

    swin_msa_kernel<<<grid, NTHREADS>>>(X, Wqkv, bqkv, Wo, bo, posb, out);
}

// round 5
// speedup vs baseline: 1.4380x; 1.0486x over previous
#include <cuda_runtime.h>

// SwinMSA fused kernel — round 3: packed fp32x2 FMA (FFMA2) + transposed tiles.
// B=16, WN=4096, S=10, E=96, H=4, dh=24.  WPB=4 windows/CTA, 288 threads.
//   phase 1: qkv = X @ W_qkv + b   (row-pair packed FFMA2, X transposed in smem)
//   phase 2: windowed attention (scalar, 160 threads), writes context transposed
//   phase 3: out = ctx @ W_o + b_o (row-pair packed FFMA2)

#define S_    10
#define E_    96
#define H_    4
#define DH_   24
#define N3_   288
#define WPB   4
#define ROWS  (WPB * S_)      // 40
#define PAD   25
#define RPAD  44              // transposed-tile row stride (floats), mult of 4
#define WN_   4096
#define NTHREADS 288

typedef unsigned long long u64;

__device__ __forceinline__ u64 fma2(u64 a, u64 b, u64 c) {
    u64 d; asm("fma.rn.f32x2 %0, %1, %2, %3;" : "=l"(d) : "l"(a), "l"(b), "l"(c)); return d;
}
__device__ __forceinline__ u64 dup2(float x) {
    u64 d; asm("mov.b64 %0, {%1, %1};" : "=l"(d) : "f"(x)); return d;
}
__device__ __forceinline__ void unpack2(u64 v, float& lo, float& hi) {
    asm("mov.b64 {%0, %1}, %2;" : "=f"(lo), "=f"(hi) : "l"(v));
}
__device__ __forceinline__ void lds_v2u64(u64& a, u64& b, unsigned addr) {
    asm volatile("ld.shared.v2.b64 {%0, %1}, [%2];" : "=l"(a), "=l"(b) : "r"(addr));
}

__global__ __launch_bounds__(NTHREADS, 3)
void swin_msa_kernel(const float* __restrict__ X,
                     const float* __restrict__ Wqkv,
                     const float* __restrict__ bqkv,
                     const float* __restrict__ Wo,
                     const float* __restrict__ bo,
                     const float* __restrict__ posb,
                     float* __restrict__ out)
{
    __shared__ __align__(16) float xt[E_ * RPAD];          // X^T, then ctx^T (4224 f)
    __shared__ float sQ[WPB * H_ * S_ * PAD];              // 4000 f each
    __shared__ float sK[WPB * H_ * S_ * PAD];
    __shared__ float sV[WPB * H_ * S_ * PAD];
    __shared__ float spb[(2 * S_ - 1) * H_];

    const int tid = threadIdx.x;
    const long wbase = (long)blockIdx.x * WPB;
    const unsigned xt_addr = (unsigned)__cvta_generic_to_shared(xt);

    // ---- load X (coalesced float4) and store transposed: xt[k][row] ----
    {
        const float4* gX4 = (const float4*)(X + wbase * (S_ * E_));
        #pragma unroll
        for (int i = tid; i < ROWS * E_ / 4; i += NTHREADS) {
            const float4 v = gX4[i];
            const int r  = i / (E_ / 4);
            const int k4 = (i % (E_ / 4)) * 4;
            xt[(k4 + 0) * RPAD + r] = v.x;
            xt[(k4 + 1) * RPAD + r] = v.y;
            xt[(k4 + 2) * RPAD + r] = v.z;
            xt[(k4 + 3) * RPAD + r] = v.w;
        }
        if (tid < (2 * S_ - 1) * H_) spb[tid] = posb[tid];
    }
    __syncthreads();

    // ---- phase 1: qkv projection. thread = 2 cols x 20 rows (10 packed pairs) ----
    {
        const int half = tid / 144;            // row half: rows [0,20) or [20,40)
        const int cidx = tid - half * 144;
        const int c0 = cidx, c1 = cidx + 144;
        const int r0 = half * 20;

        u64 a0[10], a1[10];
        {
            const u64 b0 = dup2(bqkv[c0]);
            const u64 b1 = dup2(bqkv[c1]);
            #pragma unroll
            for (int p = 0; p < 10; p++) { a0[p] = b0; a1[p] = b1; }
        }

        const float* wp0 = Wqkv + c0;
        const float* wp1 = Wqkv + c1;
        const unsigned xb0 = xt_addr + r0 * 4;

        #pragma unroll 4
        for (int k = 0; k < E_; k++) {
            const u64 w0 = dup2(wp0[k * N3_]);
            const u64 w1 = dup2(wp1[k * N3_]);
            const unsigned base = xb0 + k * (RPAD * 4);
            #pragma unroll
            for (int p = 0; p < 5; p++) {
                u64 xa, xb;
                lds_v2u64(xa, xb, base + p * 16);
                a0[2 * p]     = fma2(xa, w0, a0[2 * p]);
                a0[2 * p + 1] = fma2(xb, w0, a0[2 * p + 1]);
                a1[2 * p]     = fma2(xa, w1, a1[2 * p]);
                a1[2 * p + 1] = fma2(xb, w1, a1[2 * p + 1]);
            }
        }

        #pragma unroll
        for (int cc = 0; cc < 2; cc++) {
            const int c = cc ? c1 : c0;
            const int pp = c / E_;
            const int rem = c - pp * E_;
            const int h = rem / DH_;
            const int d = rem - h * DH_;
            const float sc = (pp == 0) ? 0.20412414523193154f /* 24^-0.5 */ : 1.0f;
            float* dst = (pp == 0) ? sQ : (pp == 1) ? sK : sV;
            #pragma unroll
            for (int p = 0; p < 10; p++) {
                float lo, hi;
                unpack2(cc ? a1[p] : a0[p], lo, hi);
                const int R0 = r0 + 2 * p;
                const int wi0 = R0 / S_, rr0 = R0 - wi0 * S_;
                const int R1 = R0 + 1;
                const int wi1 = R1 / S_, rr1 = R1 - wi1 * S_;
                dst[((wi0 * H_ + h) * S_ + rr0) * PAD + d] = lo * sc;
                dst[((wi1 * H_ + h) * S_ + rr1) * PAD + d] = hi * sc;
            }
        }
    }
    __syncthreads();

    // ---- phase 2: attention, thread = (wi, h, q), writes ctx transposed to xt ----
    if (tid < WPB * H_ * S_) {
        const int wi = tid / (H_ * S_);
        const int rem = tid - wi * (H_ * S_);
        const int h = rem / S_;
        const int q = rem - h * S_;

        const float* qrow = &sQ[((wi * H_ + h) * S_ + q) * PAD];
        float qv[DH_];
        #pragma unroll
        for (int d = 0; d < DH_; d++) qv[d] = qrow[d];

        const bool masked = (((wbase + wi) & (WN_ - 1)) == (WN_ - 1));

        float row[S_];
        #pragma unroll
        for (int kk = 0; kk < S_; kk++) {
            const float* krow = &sK[((wi * H_ + h) * S_ + kk) * PAD];
            float s = 0.0f;
            #pragma unroll
            for (int d = 0; d < DH_; d++) s += qv[d] * krow[d];
            s += spb[(kk - q + S_ - 1) * H_ + h];
            if (masked && ((q < 5) != (kk < 5))) s -= 100.0f;
            row[kk] = s;
        }

        float m = row[0];
        #pragma unroll
        for (int kk = 1; kk < S_; kk++) m = fmaxf(m, row[kk]);
        float sum = 0.0f;
        #pragma unroll
        for (int kk = 0; kk < S_; kk++) { row[kk] = __expf(row[kk] - m); sum += row[kk]; }
        const float inv = 1.0f / sum;

        const float* vbase = &sV[(wi * H_ + h) * S_ * PAD];
        const int crow = wi * S_ + q;                 // global window-row 0..39
        #pragma unroll
        for (int d = 0; d < DH_; d++) {
            float o = 0.0f;
            #pragma unroll
            for (int kk = 0; kk < S_; kk++) o += row[kk] * vbase[kk * PAD + d];
            xt[(h * DH_ + d) * RPAD + crow] = o * inv;   // ctx^T
        }
    }
    __syncthreads();

    // ---- phase 3: output projection, thread = 1 col x row-group (16/12/12 rows) ----
    {
        const int cp = tid % E_;       // output column
        const int g  = tid / E_;       // 0..2
        float* gout = out + wbase * (S_ * E_);

        if (g == 0) {
            // rows 0..15 (8 pairs)
            u64 acc[8];
            const u64 bb = dup2(bo[cp]);
            #pragma unroll
            for (int p = 0; p < 8; p++) acc[p] = bb;
            #pragma unroll 4
            for (int k = 0; k < E_; k++) {
                const u64 w = dup2(Wo[k * E_ + cp]);
                const unsigned base = xt_addr + k * (RPAD * 4);
                #pragma unroll
                for (int p = 0; p < 4; p++) {
                    u64 xa, xb;
                    lds_v2u64(xa, xb, base + p * 16);
                    acc[2 * p]     = fma2(xa, w, acc[2 * p]);
                    acc[2 * p + 1] = fma2(xb, w, acc[2 * p + 1]);
                }
            }
            #pragma unroll
            for (int p = 0; p < 8; p++) {
                float lo, hi; unpack2(acc[p], lo, hi);
                gout[(2 * p) * E_ + cp]     = lo;
                gout[(2 * p + 1) * E_ + cp] = hi;
            }
        } else {
            // g=1: rows 16..27, g=2: rows 28..39 (6 pairs each)
            const int rb = (g == 1) ? 16 : 28;
            u64 acc[6];
            const u64 bb = dup2(bo[cp]);
            #pragma unroll
            for (int p = 0; p < 6; p++) acc[p] = bb;
            const unsigned xb0 = xt_addr + rb * 4;
            #pragma unroll 4
            for (int k = 0; k < E_; k++) {
                const u64 w = dup2(Wo[k * E_ + cp]);
                const unsigned base = xb0 + k * (RPAD * 4);
                #pragma unroll
                for (int p = 0; p < 3; p++) {
                    u64 xa, xb;
                    lds_v2u64(xa, xb, base + p * 16);
                    acc[2 * p]     = fma2(xa, w, acc[2 * p]);
                    acc[2 * p + 1] = fma2(xb, w, acc[2 * p + 1]);
                }
            }
            #pragma unroll
            for (int p = 0; p < 6; p++) {
                float lo, hi; unpack2(acc[p], lo, hi);
                gout[(rb + 2 * p) * E_ + cp]     = lo;
                gout[(rb + 2 * p + 1) * E_ + cp] = hi;
            }
        }
    }
}

extern "C" void kernel_launch(void* const* d_in, const int* in_sizes, int n_in,
                              void* d_out, int out_size)
{
    const float* X    = (const float*)d_in[0];
    const float* Wqkv = (const float*)d_in[1];
    const float* bqkv = (const float*)d_in[2];
    const float* Wo   = (const float*)d_in[3];
    const float* bo   = (const float*)d_in[4];
    const float* posb = (const float*)d_in[5];
    float* out = (float*)d_out;

    const int n_windows = in_sizes[0] / (S_ * E_);   // 65536
    const int grid = n_windows / WPB;                // 16384

    swin_msa_kernel<<<grid, NTHREADS>>>(X, Wqkv, bqkv, Wo, bo, posb, out);
}

// round 9
// speedup vs baseline: 1.7460x; 1.2142x over previous
#include <cuda_runtime.h>

// SwinMSA fused kernel — round 4: FFMA2 + 4-column register tiling (C=4).
// B=16, WN=4096, S=10, E=96, H=4, dh=24.  WPB=4 windows/CTA, 288 threads.
//   phase 1: qkv = X @ W_qkv + b   (thread = 4 adjacent cols x 10 rows, FFMA2)
//   phase 2: windowed attention (scalar, 160 threads), writes context transposed
//   phase 3: out = ctx @ W_o + b_o (thread = 4 adjacent cols x 4 rows, FFMA2)

#define S_    10
#define E_    96
#define H_    4
#define DH_   24
#define N3_   288
#define WPB   4
#define ROWS  (WPB * S_)      // 40
#define PAD   25
#define RPAD  44              // transposed-tile row stride (floats)
#define WN_   4096
#define NTHREADS 288

typedef unsigned long long u64;

__device__ __forceinline__ u64 fma2(u64 a, u64 b, u64 c) {
    u64 d; asm("fma.rn.f32x2 %0, %1, %2, %3;" : "=l"(d) : "l"(a), "l"(b), "l"(c)); return d;
}
__device__ __forceinline__ u64 dup2(float x) {
    u64 d; asm("mov.b64 %0, {%1, %1};" : "=l"(d) : "f"(x)); return d;
}
__device__ __forceinline__ void unpack2(u64 v, float& lo, float& hi) {
    asm("mov.b64 {%0, %1}, %2;" : "=f"(lo), "=f"(hi) : "l"(v));
}

__global__ __launch_bounds__(NTHREADS, 3)
void swin_msa_kernel(const float* __restrict__ X,
                     const float* __restrict__ Wqkv,
                     const float* __restrict__ bqkv,
                     const float* __restrict__ Wo,
                     const float* __restrict__ bo,
                     const float* __restrict__ posb,
                     float* __restrict__ out)
{
    __shared__ __align__(16) float xt[E_ * RPAD];          // X^T, then ctx^T
    __shared__ float sQ[WPB * H_ * S_ * PAD];
    __shared__ float sK[WPB * H_ * S_ * PAD];
    __shared__ float sV[WPB * H_ * S_ * PAD];
    __shared__ float spb[(2 * S_ - 1) * H_];

    const int tid = threadIdx.x;
    const long wbase = (long)blockIdx.x * WPB;

    // ---- load X (coalesced float4) and store transposed: xt[k][row] ----
    {
        const float4* gX4 = (const float4*)(X + wbase * (S_ * E_));
        #pragma unroll
        for (int i = tid; i < ROWS * E_ / 4; i += NTHREADS) {
            const float4 v = gX4[i];
            const int r  = i / (E_ / 4);
            const int k4 = (i % (E_ / 4)) * 4;
            xt[(k4 + 0) * RPAD + r] = v.x;
            xt[(k4 + 1) * RPAD + r] = v.y;
            xt[(k4 + 2) * RPAD + r] = v.z;
            xt[(k4 + 3) * RPAD + r] = v.w;
        }
        if (tid < (2 * S_ - 1) * H_) spb[tid] = posb[tid];
    }
    __syncthreads();

    // ---- phase 1: qkv projection. thread = 4 adjacent cols x 10 rows ----
    {
        const int cg = tid % 72;           // column quad
        const int rq = tid / 72;           // row quarter == window index
        const int c0 = 4 * cg;
        const int r0 = 10 * rq;

        u64 acc[4][5];
        {
            const float4 b4 = *(const float4*)&bqkv[c0];
            const u64 b0 = dup2(b4.x), b1 = dup2(b4.y), b2 = dup2(b4.z), b3 = dup2(b4.w);
            #pragma unroll
            for (int p = 0; p < 5; p++) {
                acc[0][p] = b0; acc[1][p] = b1; acc[2][p] = b2; acc[3][p] = b3;
            }
        }

        const float4* wq4 = (const float4*)(Wqkv + c0);   // stride 72 float4 per k
        const float* xrow = xt + r0;

        #pragma unroll 2
        for (int k = 0; k < E_; k++) {
            const float4 w = wq4[k * (N3_ / 4)];
            const u64 w0 = dup2(w.x), w1 = dup2(w.y), w2 = dup2(w.z), w3 = dup2(w.w);
            const float* xk = xrow + k * RPAD;
            #pragma unroll
            for (int p = 0; p < 5; p++) {
                const u64 x2 = *(const u64*)(xk + 2 * p);   // rows r0+2p, r0+2p+1
                acc[0][p] = fma2(x2, w0, acc[0][p]);
                acc[1][p] = fma2(x2, w1, acc[1][p]);
                acc[2][p] = fma2(x2, w2, acc[2][p]);
                acc[3][p] = fma2(x2, w3, acc[3][p]);
            }
        }

        // scatter to sQ/sK/sV (all 10 rows belong to window rq)
        #pragma unroll
        for (int j = 0; j < 4; j++) {
            const int c = c0 + j;
            const int pp = c / E_;
            const int rem = c - pp * E_;
            const int h = rem / DH_;
            const int d = rem - h * DH_;
            const float sc = (pp == 0) ? 0.20412414523193154f /* 24^-0.5 */ : 1.0f;
            float* dst = ((pp == 0) ? sQ : (pp == 1) ? sK : sV)
                         + ((rq * H_ + h) * S_) * PAD + d;
            #pragma unroll
            for (int p = 0; p < 5; p++) {
                float lo, hi;
                unpack2(acc[j][p], lo, hi);
                dst[(2 * p) * PAD]     = lo * sc;
                dst[(2 * p + 1) * PAD] = hi * sc;
            }
        }
    }
    __syncthreads();

    // ---- phase 2: attention, thread = (wi, h, q), writes ctx^T to xt ----
    if (tid < WPB * H_ * S_) {
        const int wi = tid / (H_ * S_);
        const int rem = tid - wi * (H_ * S_);
        const int h = rem / S_;
        const int q = rem - h * S_;

        const float* qrow = &sQ[((wi * H_ + h) * S_ + q) * PAD];
        float qv[DH_];
        #pragma unroll
        for (int d = 0; d < DH_; d++) qv[d] = qrow[d];

        const bool masked = (((wbase + wi) & (WN_ - 1)) == (WN_ - 1));

        float row[S_];
        #pragma unroll
        for (int kk = 0; kk < S_; kk++) {
            const float* krow = &sK[((wi * H_ + h) * S_ + kk) * PAD];
            float s = 0.0f;
            #pragma unroll
            for (int d = 0; d < DH_; d++) s += qv[d] * krow[d];
            s += spb[(kk - q + S_ - 1) * H_ + h];
            if (masked && ((q < 5) != (kk < 5))) s -= 100.0f;
            row[kk] = s;
        }

        float m = row[0];
        #pragma unroll
        for (int kk = 1; kk < S_; kk++) m = fmaxf(m, row[kk]);
        float sum = 0.0f;
        #pragma unroll
        for (int kk = 0; kk < S_; kk++) { row[kk] = __expf(row[kk] - m); sum += row[kk]; }
        const float inv = 1.0f / sum;

        const float* vbase = &sV[(wi * H_ + h) * S_ * PAD];
        const int crow = wi * S_ + q;                 // global window-row 0..39
        #pragma unroll
        for (int d = 0; d < DH_; d++) {
            float o = 0.0f;
            #pragma unroll
            for (int kk = 0; kk < S_; kk++) o += row[kk] * vbase[kk * PAD + d];
            xt[(h * DH_ + d) * RPAD + crow] = o * inv;   // ctx^T
        }
    }
    __syncthreads();

    // ---- phase 3: output projection. thread = 4 adjacent cols x 4 rows ----
    if (tid < 240) {
        const int cg = tid % 24;           // column quad (cols 4cg..4cg+3)
        const int rg = tid / 24;           // row group (rows 4rg..4rg+3)
        const int c0 = 4 * cg;
        const int r0 = 4 * rg;

        u64 acc[4][2];
        {
            const float4 b4 = *(const float4*)&bo[c0];
            acc[0][0] = acc[0][1] = dup2(b4.x);
            acc[1][0] = acc[1][1] = dup2(b4.y);
            acc[2][0] = acc[2][1] = dup2(b4.z);
            acc[3][0] = acc[3][1] = dup2(b4.w);
        }

        const float4* wo4 = (const float4*)(Wo + c0);    // stride 24 float4 per k
        const float* xrow = xt + r0;

        #pragma unroll 4
        for (int k = 0; k < E_; k++) {
            const float4 w = wo4[k * (E_ / 4)];
            const u64 w0 = dup2(w.x), w1 = dup2(w.y), w2 = dup2(w.z), w3 = dup2(w.w);
            const float* xk = xrow + k * RPAD;
            const u64 xa = *(const u64*)(xk);        // rows r0, r0+1
            const u64 xb = *(const u64*)(xk + 2);    // rows r0+2, r0+3
            acc[0][0] = fma2(xa, w0, acc[0][0]);  acc[0][1] = fma2(xb, w0, acc[0][1]);
            acc[1][0] = fma2(xa, w1, acc[1][0]);  acc[1][1] = fma2(xb, w1, acc[1][1]);
            acc[2][0] = fma2(xa, w2, acc[2][0]);  acc[2][1] = fma2(xb, w2, acc[2][1]);
            acc[3][0] = fma2(xa, w3, acc[3][0]);  acc[3][1] = fma2(xb, w3, acc[3][1]);
        }

        // write 4 rows x 4 cols as coalesced STG.128
        float* gout = out + wbase * (S_ * E_);
        #pragma unroll
        for (int i = 0; i < 4; i++) {
            const int pr = i >> 1;          // which u64 pair
            float4 o;
            float lo, hi;
            unpack2(acc[0][pr], lo, hi); o.x = (i & 1) ? hi : lo;
            unpack2(acc[1][pr], lo, hi); o.y = (i & 1) ? hi : lo;
            unpack2(acc[2][pr], lo, hi); o.z = (i & 1) ? hi : lo;
            unpack2(acc[3][pr], lo, hi); o.w = (i & 1) ? hi : lo;
            *(float4*)&gout[(r0 + i) * E_ + c0] = o;
        }
    }
}

extern "C" void kernel_launch(void* const* d_in, const int* in_sizes, int n_in,
                              void* d_out, int out_size)
{
    const float* X    = (const float*)d_in[0];
    const float* Wqkv = (const float*)d_in[1];
    const float* bqkv = (const float*)d_in[2];
    const float* Wo   = (const float*)d_in[3];
    const float* bo   = (const float*)d_in[4];
    const float* posb = (const float*)d_in[5];
    float* out = (float*)d_out;

    const int n_windows = in_sizes[0] / (S_ * E_);   // 65536
    const int grid = n_windows / WPB;                // 16384

    swin_msa_kernel<<<grid, NTHREADS>>>(X, Wqkv, bqkv, Wo, bo, posb, out);
}